// round 17
// baseline (speedup 1.0000x reference)
#include <cuda_runtime.h>
#include <cuda_fp16.h>
#include <math.h>
#include <cstdint>

// ---------------------------------------------------------------------------
// Problem constants (B=4, S=4096, D=1024)
// ---------------------------------------------------------------------------
#define MM    16384
#define DDIM  1024
#define NELEM ((size_t)MM * DDIM)

#define WSCALE     64.0f
#define INV_WSCALE (1.0f / 64.0f)

// fp16 intermediates
__device__ __half g_val[NELEM];
__device__ __half g_kc [NELEM];
__device__ __half g_ks [NELEM];
__device__ __half g_qc [NELEM];
__device__ __half g_qs [NELEM];
__device__ __half g_xh[NELEM];
__device__ __half g_kh[NELEM];
// weight slots (all x64-scaled fp16):
// 0 = Wv^T, 1 = Wkc^T (composed), 2 = Wqc^T (composed), 3 = Wo^T,
// 4 = Wkp^T, 5 = Wqp^T, 6 = Wk (row-major), 7 = Wq (row-major)
__device__ __half g_w[8][(size_t)DDIM * DDIM];
__device__ float g_beff[2 * DDIM];
__device__ float g_ortho_part[8192];

// ---------------------------------------------------------------------------
// Warp-MMA helpers (baseline PTX: sm_80 features only)
// ---------------------------------------------------------------------------
__device__ __forceinline__ uint32_t smem_u32(const void* p) {
    return (uint32_t)__cvta_generic_to_shared(p);
}

__device__ __forceinline__ void ldsm_x4(uint32_t* r, uint32_t addr) {
    asm volatile("ldmatrix.sync.aligned.m8n8.x4.shared.b16 {%0,%1,%2,%3}, [%4];"
                 : "=r"(r[0]), "=r"(r[1]), "=r"(r[2]), "=r"(r[3]) : "r"(addr));
}

__device__ __forceinline__ void mma16816(float* d, const uint32_t* a, const uint32_t* b) {
    asm volatile(
        "mma.sync.aligned.m16n8k16.row.col.f32.f16.f16.f32 "
        "{%0,%1,%2,%3}, {%4,%5,%6,%7}, {%8,%9}, {%0,%1,%2,%3};"
        : "+f"(d[0]), "+f"(d[1]), "+f"(d[2]), "+f"(d[3])
        : "r"(a[0]), "r"(a[1]), "r"(a[2]), "r"(a[3]), "r"(b[0]), "r"(b[1]));
}

#define CP_ASYNC16(dst, src) \
    asm volatile("cp.async.cg.shared.global [%0], [%1], 16;" :: "r"(dst), "l"(src))
#define CP_COMMIT() asm volatile("cp.async.commit_group;" ::: "memory")
#define CP_WAIT1()  asm volatile("cp.async.wait_group 1;" ::: "memory")
#define CP_WAIT0()  asm volatile("cp.async.wait_group 0;" ::: "memory")

// ---------------------------------------------------------------------------
// fp16 single-pass GEMM (unchanged from R16)
// ---------------------------------------------------------------------------
#define GBM 256
#define GBN 128
#define GBK 64
#define NTHREADS 512
#define ROWB 144
#define A_TILEB (GBM * ROWB)
#define B_TILEB (GBN * ROWB)
#define STAGEB (A_TILEB + B_TILEB)
#define GSTAGES 3
#define GSMEM (GSTAGES * STAGEB)       // 165888 B

template <int ROWS>
__device__ __forceinline__ void ld_tile(uint32_t sdst, const __half* g,
                                        int K, int k0, int tid) {
    #pragma unroll
    for (int t = 0; t < ROWS * 8 / NTHREADS; ++t) {
        const int c   = tid + t * NTHREADS;
        const int row = c >> 3;
        const int cc  = c & 7;
        CP_ASYNC16(sdst + row * ROWB + cc * 16,
                   g + (size_t)row * K + k0 + cc * 8);
    }
}

template <int EPI>
__global__ void __launch_bounds__(NTHREADS, 1) mma_gemm(
    const __half* __restrict__ A,  const __half* __restrict__ A2,
    const __half* __restrict__ W,  const __half* __restrict__ W2,
    const float* __restrict__ b0, const float* __restrict__ b1,
    const float* __restrict__ b2,
    float* __restrict__ of0,
    __half* __restrict__ oh0, __half* __restrict__ oh1,
    __half* __restrict__ oh2, __half* __restrict__ oh3,
    __half* __restrict__ oh4,
    const float* __restrict__ resid,
    int M, int N, int K)
{
    extern __shared__ __align__(128) char smem[];
    const uint32_t sb = smem_u32(smem);
    const int tid  = threadIdx.x;
    const int wid  = tid >> 5, lane = tid & 31;
    const int wm   = (wid >> 2) * 64;
    const int wn   = (wid & 3) * 32;
    const int m0   = blockIdx.y * GBM, n0 = blockIdx.x * GBN;
    const int z    = (EPI == 6) ? (int)blockIdx.z : 0;

    const __half* Ap = (EPI == 6 && z) ? A2 : A;
    const __half* Wp = (EPI == 6 && z) ? W2 : W;

    const __half* A0 = Ap + (size_t)m0 * K;
    const __half* B0 = Wp + (size_t)n0 * K;

    const int KT = K / GBK;

    #pragma unroll
    for (int p = 0; p < 2; ++p) {
        const uint32_t st = sb + p * STAGEB;
        ld_tile<GBM>(st, A0, K, p * GBK, tid);
        ld_tile<GBN>(st + A_TILEB, B0, K, p * GBK, tid);
        CP_COMMIT();
    }

    float acc[4][4][4];
    #pragma unroll
    for (int i = 0; i < 4; ++i)
        #pragma unroll
        for (int j = 0; j < 4; ++j)
            #pragma unroll
            for (int e = 0; e < 4; ++e) acc[i][j][e] = 0.0f;

    const int aRow = lane & 15;
    const int aCol = lane & 16;
    const int bRow = (lane & 7) + ((lane & 16) >> 1);
    const int bCol = (lane & 8) * 2;

    for (int kt = 0; kt < KT; ++kt) {
        if (kt + 1 < KT) { CP_WAIT1(); } else { CP_WAIT0(); }
        __syncthreads();

        if (kt + 2 < KT) {
            const uint32_t st = sb + ((kt + 2) % GSTAGES) * STAGEB;
            const int k0 = (kt + 2) * GBK;
            ld_tile<GBM>(st, A0, K, k0, tid);
            ld_tile<GBN>(st + A_TILEB, B0, K, k0, tid);
            CP_COMMIT();
        }

        const uint32_t st = sb + (kt % GSTAGES) * STAGEB;
        const uint32_t sA = st;
        const uint32_t sB = st + A_TILEB;

        #pragma unroll
        for (int h = 0; h < 4; ++h) {
            const int kb = h * 32;

            uint32_t a[4][4], b[2][4];
            #pragma unroll
            for (int mi = 0; mi < 4; ++mi) {
                const uint32_t off = (uint32_t)(wm + mi * 16 + aRow) * ROWB + kb + aCol;
                ldsm_x4(a[mi], sA + off);
            }
            #pragma unroll
            for (int bi = 0; bi < 2; ++bi) {
                const uint32_t off = (uint32_t)(wn + bi * 16 + bRow) * ROWB + kb + bCol;
                ldsm_x4(b[bi], sB + off);
            }

            #pragma unroll
            for (int mi = 0; mi < 4; ++mi) {
                #pragma unroll
                for (int ni = 0; ni < 4; ++ni) {
                    mma16816(acc[mi][ni], a[mi], &b[ni >> 1][(ni & 1) * 2]);
                }
            }
        }
    }

    // epilogue
    #pragma unroll
    for (int mi = 0; mi < 4; ++mi) {
        #pragma unroll
        for (int ni = 0; ni < 4; ++ni) {
            const int nn = n0 + wn + ni * 8 + (lane & 3) * 2;
            #pragma unroll
            for (int half_ = 0; half_ < 2; ++half_) {
                const int row = m0 + wm + mi * 16 + (lane >> 2) + half_ * 8;
                float v0 = acc[mi][ni][half_ * 2 + 0] * INV_WSCALE;
                float v1 = acc[mi][ni][half_ * 2 + 1] * INV_WSCALE;
                if (EPI == 5) {
                    const int sel  = nn >> 10;
                    const int cold = nn & 1023;
                    const float* bp = (sel == 0) ? b0 : (sel == 1) ? b1 : b2;
                    const float2 bv = *(const float2*)(bp + cold);
                    v0 += bv.x; v1 += bv.y;
                    const size_t off = (size_t)row * DDIM + cold;
                    if (sel == 0) {
                        *(__half2*)(oh0 + off) = __floats2half2_rn(v0, v1);
                    } else {
                        float s0, c0, s1, c1;
                        __sincosf(v0, &s0, &c0);
                        __sincosf(v1, &s1, &c1);
                        __half* oc = (sel == 1) ? oh1 : oh3;
                        __half* os = (sel == 1) ? oh2 : oh4;
                        *(__half2*)(oc + off) = __floats2half2_rn(c0, c1);
                        *(__half2*)(os + off) = __floats2half2_rn(s0, s1);
                    }
                } else if (EPI == 6) {
                    __half* op = z ? oh1 : oh0;
                    *(__half2*)(op + (size_t)row * N + nn) =
                        __floats2half2_rn(v0, v1);
                } else {   // EPI 3
                    const float2 bv = *(const float2*)(b0 + nn);
                    const size_t off = (size_t)row * N + nn;
                    const float2 rv = *(const float2*)(resid + off);
                    *(float2*)(of0 + off) = make_float2(v0 + bv.x + rv.x,
                                                        v1 + bv.y + rv.y);
                }
            }
        }
    }
}

// ---------------------------------------------------------------------------
// fp32 -> fp16 with scale
// ---------------------------------------------------------------------------
__global__ __launch_bounds__(256)
void f32_to_f16s(const float* __restrict__ a, __half* __restrict__ h,
                 float scale, int n4)
{
    const int i = blockIdx.x * 256 + threadIdx.x;
    if (i >= n4) return;
    const float4 v = ((const float4*)a)[i];
    __half2* H = (__half2*)h;
    H[2 * i]     = __floats2half2_rn(v.x * scale, v.y * scale);
    H[2 * i + 1] = __floats2half2_rn(v.z * scale, v.w * scale);
}

struct C2 { const float* src[2]; };
__global__ __launch_bounds__(256)
void f16conv2(C2 c, __half* __restrict__ outbase, size_t wsz, int n4)
{
    const float* a = c.src[blockIdx.z];
    __half* h = outbase + blockIdx.z * wsz;
    const int i = blockIdx.x * 256 + threadIdx.x;
    if (i >= n4) return;
    const float4 v = ((const float4*)a)[i];
    __half2* H = (__half2*)h;
    H[2 * i]     = __floats2half2_rn(v.x * WSCALE, v.y * WSCALE);
    H[2 * i + 1] = __floats2half2_rn(v.z * WSCALE, v.w * WSCALE);
}

struct WT4 { const float* src[4]; int slot[4]; };
__global__ __launch_bounds__(1024)
void wtransT(WT4 ws, __half* __restrict__ outbase, int Kd, int Nd)
{
    __shared__ float t[32][33];
    const float* W = ws.src[blockIdx.z];
    __half* th = outbase + (size_t)ws.slot[blockIdx.z] * Kd * Nd;
    const int tx = threadIdx.x, ty = threadIdx.y;
    const int k0 = blockIdx.y * 32, n0 = blockIdx.x * 32;
    t[ty][tx] = W[(size_t)(k0 + ty) * Nd + n0 + tx];
    __syncthreads();
    const float v = t[tx][ty] * WSCALE;
    th[(size_t)(n0 + ty) * Kd + k0 + tx] = __float2half(v);
}

__global__ __launch_bounds__(256)
void bias_eff16(const float* __restrict__ bin0, const __half* __restrict__ Wt0,
                const float* __restrict__ badd0,
                const float* __restrict__ bin1, const __half* __restrict__ Wt1,
                const float* __restrict__ badd1,
                float* __restrict__ beff, int D)
{
    const int nidx = blockIdx.x;
    const int zi   = blockIdx.z;
    const float* bin  = zi ? bin1 : bin0;
    const float* badd = zi ? badd1 : badd0;
    const __half* row = (zi ? Wt1 : Wt0) + (size_t)nidx * D;

    float acc = 0.0f;
    for (int d = threadIdx.x; d < D; d += 256)
        acc = fmaf(bin[d], __half2float(row[d]), acc);

    __shared__ float sh[32];
    const int lane = threadIdx.x & 31, w = threadIdx.x >> 5;
    #pragma unroll
    for (int o = 16; o; o >>= 1) acc += __shfl_down_sync(0xffffffffu, acc, o);
    if (lane == 0) sh[w] = acc;
    __syncthreads();
    if (w == 0) {
        acc = (lane < 8) ? sh[lane] : 0.0f;
        #pragma unroll
        for (int o = 4; o; o >>= 1) acc += __shfl_down_sync(0xffffffffu, acc, o);
        if (lane == 0) beff[zi * D + nidx] = acc * INV_WSCALE + badd[nidx];
    }
}

// ---------------------------------------------------------------------------
// FUSED chunked cumsum + retrieve + LayerNorm -> fp16 kh (R15 version)
// ---------------------------------------------------------------------------
#define CLN_T 512
__global__ __launch_bounds__(CLN_T)
void cumsum_ln(const __half* __restrict__ value,
               const __half* __restrict__ kc, const __half* __restrict__ ks,
               const __half* __restrict__ qc, const __half* __restrict__ qs,
               const float* __restrict__ gamma, const float* __restrict__ beta,
               __half* __restrict__ okh,
               int Bb, int S, int D,
               const int* __restrict__ cs_ptr, float inv_sqrt_S)
{
    const int cs = cs_ptr[0];
    const int nc = (S + cs - 1) / cs;
    const int total = Bb * nc;
    const int tid = threadIdx.x;
    const int D2 = D >> 1;
    const int c0 = tid;

    const __half2* V2 = (const __half2*)value;
    const __half2* KC = (const __half2*)kc;
    const __half2* KS = (const __half2*)ks;
    const __half2* QC = (const __half2*)qc;
    const __half2* QS = (const __half2*)qs;
    __half2* OK = (__half2*)okh;

    const float2 ga = *(const float2*)(gamma + 2 * c0);
    const float2 bt = *(const float2*)(beta  + 2 * c0);

    __shared__ float s1[4][16], s2[4][16];
    __shared__ float sMean[4], sRstd[4];
    const int lane = tid & 31, w = tid >> 5;
    const float invD = 1.0f / (float)D;

    for (int t = blockIdx.x; t < total; t += gridDim.x) {
        const int b  = t / nc;
        const int s0 = (t % nc) * cs;
        const int smax = min(cs, S - s0);
        const size_t base = ((size_t)b * S + s0) * D2 + c0;

        float rr = 0.0f, ii = 0.0f;
        float rr2 = 0.0f, ii2 = 0.0f;

        for (int sq0 = 0; sq0 < smax; sq0 += 4) {
            const int R = min(4, smax - sq0);

            __half2 pv[4], pkc[4], pks[4], pqc[4], pqs[4];
            #pragma unroll
            for (int r = 0; r < 4; ++r) {
                if (r < R) {
                    const size_t o = base + (size_t)(sq0 + r) * D2;
                    pv[r]  = V2[o];
                    pkc[r] = KC[o];
                    pks[r] = KS[o];
                    pqc[r] = QC[o];
                    pqs[r] = QS[o];
                }
            }

            float tx[4], ty[4];
            #pragma unroll
            for (int r = 0; r < 4; ++r) {
                if (r < R) {
                    const float2 vv = __half22float2(pv[r]);
                    const float2 cc = __half22float2(pkc[r]);
                    const float2 ss = __half22float2(pks[r]);
                    rr  = fmaf(vv.x, cc.x, rr);
                    rr2 = fmaf(vv.y, cc.y, rr2);
                    ii  = fmaf(vv.x, ss.x, ii);
                    ii2 = fmaf(vv.y, ss.y, ii2);
                    const float2 qcc = __half22float2(pqc[r]);
                    const float2 qss = __half22float2(pqs[r]);
                    tx[r] = (rr  * qcc.x + ii  * qss.x) * inv_sqrt_S;
                    ty[r] = (rr2 * qcc.y + ii2 * qss.y) * inv_sqrt_S;
                } else { tx[r] = 0.0f; ty[r] = 0.0f; }
            }

            float sum[4], sqv[4];
            #pragma unroll
            for (int r = 0; r < 4; ++r) {
                sum[r] = tx[r] + ty[r];
                sqv[r] = tx[r] * tx[r] + ty[r] * ty[r];
                #pragma unroll
                for (int o = 16; o; o >>= 1) {
                    sum[r] += __shfl_down_sync(0xffffffffu, sum[r], o);
                    sqv[r] += __shfl_down_sync(0xffffffffu, sqv[r], o);
                }
            }
            if (lane == 0) {
                #pragma unroll
                for (int r = 0; r < 4; ++r) { s1[r][w] = sum[r]; s2[r][w] = sqv[r]; }
            }
            __syncthreads();
            if (w == 0 && lane < 4) {
                float su = 0.0f, qu = 0.0f;
                #pragma unroll
                for (int k = 0; k < 16; ++k) { su += s1[lane][k]; qu += s2[lane][k]; }
                const float mean = su * invD;
                const float var  = qu * invD - mean * mean;
                sMean[lane] = mean;
                sRstd[lane] = rsqrtf(var + 1e-5f);
            }
            __syncthreads();

            #pragma unroll
            for (int r = 0; r < 4; ++r) {
                if (r < R) {
                    const float mean = sMean[r], rstd = sRstd[r];
                    const size_t o = base + (size_t)(sq0 + r) * D2;
                    OK[o] = __floats2half2_rn(
                        (tx[r] - mean) * rstd * ga.x + bt.x,
                        (ty[r] - mean) * rstd * ga.y + bt.y);
                }
            }
        }
    }
}

// ---------------------------------------------------------------------------
// Ortho loss
// ---------------------------------------------------------------------------
__global__ __launch_bounds__(256)
void ortho_partial(const __half* __restrict__ kc, const __half* __restrict__ ks,
                   const int* __restrict__ idx, int S, int D, int n)
{
    const int t = blockIdx.x;
    const int j = t % n;
    const int i = (t / n) % n;
    const int b = t / (n * n);

    if (i == j) {
        if (threadIdx.x == 0) g_ortho_part[t] = 0.0f;
        return;
    }
    const int si = idx[i], sj = idx[j];
    const __half* ci = kc + ((size_t)b * S + si) * D;
    const __half* cj = kc + ((size_t)b * S + sj) * D;
    const __half* ni = ks + ((size_t)b * S + si) * D;
    const __half* nj = ks + ((size_t)b * S + sj) * D;

    float acc = 0.0f;
    for (int d = threadIdx.x; d < D; d += blockDim.x) {
        const float v = __half2float(ci[d]) * __half2float(cj[d])
                      + __half2float(ni[d]) * __half2float(nj[d]);
        acc = fmaf(v, v, acc);
    }

    __shared__ float sh[32];
    const int lane = threadIdx.x & 31, w = threadIdx.x >> 5;
    #pragma unroll
    for (int o = 16; o; o >>= 1) acc += __shfl_down_sync(0xffffffffu, acc, o);
    if (lane == 0) sh[w] = acc;
    __syncthreads();
    if (w == 0) {
        acc = (lane < 8) ? sh[lane] : 0.0f;
        #pragma unroll
        for (int o = 4; o; o >>= 1) acc += __shfl_down_sync(0xffffffffu, acc, o);
        if (lane == 0) g_ortho_part[t] = acc;
    }
}

__global__ __launch_bounds__(256)
void ortho_reduce(float* __restrict__ out_loc, int total, float denom)
{
    float acc = 0.0f;
    for (int t = threadIdx.x; t < total; t += 256) acc += g_ortho_part[t];

    __shared__ float sh[32];
    const int lane = threadIdx.x & 31, w = threadIdx.x >> 5;
    #pragma unroll
    for (int o = 16; o; o >>= 1) acc += __shfl_down_sync(0xffffffffu, acc, o);
    if (lane == 0) sh[w] = acc;
    __syncthreads();
    if (w == 0) {
        acc = (lane < 8) ? sh[lane] : 0.0f;
        #pragma unroll
        for (int o = 4; o; o >>= 1) acc += __shfl_down_sync(0xffffffffu, acc, o);
        if (lane == 0) *out_loc = acc / denom;
    }
}

// ---------------------------------------------------------------------------
// Launcher: fork/join + M-split pipelining of the heavy stages
// ---------------------------------------------------------------------------
static cudaStream_t g_s1, g_s2;
static cudaEvent_t  g_ev[8];
static int g_res_init = 0;

extern "C" void kernel_launch(void* const* d_in, const int* in_sizes, int n_in,
                              void* d_out, int out_size)
{
    if (!g_res_init) {
        cudaStreamCreateWithFlags(&g_s1, cudaStreamNonBlocking);
        cudaStreamCreateWithFlags(&g_s2, cudaStreamNonBlocking);
        for (int i = 0; i < 8; ++i)
            cudaEventCreateWithFlags(&g_ev[i], cudaEventDisableTiming);
        g_res_init = 1;
    }

    const float* x    = (const float*)d_in[0];
    const float* Wk   = (const float*)d_in[1];
    const float* bk   = (const float*)d_in[2];
    const float* Wv   = (const float*)d_in[3];
    const float* bv   = (const float*)d_in[4];
    const float* Wq   = (const float*)d_in[5];
    const float* bq   = (const float*)d_in[6];
    const float* Wkp  = (const float*)d_in[7];
    const float* bkp  = (const float*)d_in[8];
    const float* Wqp  = (const float*)d_in[9];
    const float* bqp  = (const float*)d_in[10];
    const float* ln_g = (const float*)d_in[11];
    const float* ln_b = (const float*)d_in[12];
    const float* Wo   = (const float*)d_in[13];
    const float* bo   = (const float*)d_in[14];
    const int*   idx  = (const int*)d_in[15];
    const int*   csp  = (const int*)d_in[16];

    const int D  = in_sizes[2];        // 1024
    const int M  = in_sizes[0] / D;    // 16384
    const int Bb = 4;
    const int S  = M / Bb;             // 4096
    const int n  = in_sizes[15];       // 32

    __half *val, *kc, *ks, *qc, *qs, *xh, *kh, *wbase;
    float* beff;
    cudaGetSymbolAddress((void**)&val, g_val);
    cudaGetSymbolAddress((void**)&kc,  g_kc);
    cudaGetSymbolAddress((void**)&ks,  g_ks);
    cudaGetSymbolAddress((void**)&qc,  g_qc);
    cudaGetSymbolAddress((void**)&qs,  g_qs);
    cudaGetSymbolAddress((void**)&xh,  g_xh);
    cudaGetSymbolAddress((void**)&kh,  g_kh);
    cudaGetSymbolAddress((void**)&wbase, g_w);
    cudaGetSymbolAddress((void**)&beff, g_beff);
    const size_t WSZ = (size_t)D * D;
    #define WSLOT(i) (wbase + (size_t)(i) * WSZ)

    float* out = (float*)d_out;

    cudaFuncSetAttribute(mma_gemm<3>, cudaFuncAttributeMaxDynamicSharedMemorySize, GSMEM);
    cudaFuncSetAttribute(mma_gemm<5>, cudaFuncAttributeMaxDynamicSharedMemorySize, GSMEM);
    cudaFuncSetAttribute(mma_gemm<6>, cudaFuncAttributeMaxDynamicSharedMemorySize, GSMEM);

    const int n4w = (int)(WSZ / 4);
    const int n4  = (int)(NELEM / 4);

    const int Mh = M / 2;                       // 8192 rows per half
    const size_t offE = (size_t)Mh * D;         // element offset per half
    const float inv_sqrt_S = 1.0f / sqrtf((float)S);
    const float denom = (float)(n * (n - 1)) * (float)D + 1e-6f;

    // ---- fork: weights on s1, x conversion on default ----
    cudaEventRecord(g_ev[0], 0);
    cudaStreamWaitEvent(g_s1, g_ev[0], 0);

    f32_to_f16s<<<(n4 + 255) / 256, 256>>>(x, xh, 1.0f, n4);

    WT4 wt;
    wt.src[0] = Wv;  wt.slot[0] = 0;
    wt.src[1] = Wo;  wt.slot[1] = 3;
    wt.src[2] = Wkp; wt.slot[2] = 4;
    wt.src[3] = Wqp; wt.slot[3] = 5;
    wtransT<<<dim3(D / 32, D / 32, 4), dim3(32, 32), 0, g_s1>>>(wt, wbase, D, D);

    C2 c2; c2.src[0] = Wk; c2.src[1] = Wq;
    f16conv2<<<dim3((n4w + 255) / 256, 1, 2), 256, 0, g_s1>>>(c2, WSLOT(6), WSZ, n4w);

    bias_eff16<<<dim3(D, 1, 2), 256, 0, g_s1>>>(bk, WSLOT(4), bkp,
                                                bq, WSLOT(5), bqp, beff, D);

    mma_gemm<6><<<dim3(D / GBN, D / GBM, 2), NTHREADS, GSMEM, g_s1>>>(
        WSLOT(4), WSLOT(5), WSLOT(6), WSLOT(7), nullptr, nullptr, nullptr,
        nullptr, WSLOT(1), WSLOT(2), nullptr, nullptr, nullptr, nullptr,
        D, D, D);

    cudaEventRecord(g_ev[1], g_s1);
    cudaStreamWaitEvent(0, g_ev[1], 0);

    // ---- pipelined heavy stages (M split in halves) ----
    const dim3 megaGrid(3 * D / GBN, Mh / GBM);
    const dim3 outGrid(D / GBN, Mh / GBM);

    // mega GEMM half 0
    mma_gemm<5><<<megaGrid, NTHREADS, GSMEM>>>(
        xh, nullptr, WSLOT(0), nullptr, bv, beff, beff + D,
        nullptr, val, kc, ks, qc, qs, nullptr, Mh, 3 * D, D);
    cudaEventRecord(g_ev[2], 0);

    // mega GEMM half 1 (default)
    mma_gemm<5><<<megaGrid, NTHREADS, GSMEM>>>(
        xh + offE, nullptr, WSLOT(0), nullptr, bv, beff, beff + D,
        nullptr, val + offE, kc + offE, ks + offE, qc + offE, qs + offE,
        nullptr, Mh, 3 * D, D);
    cudaEventRecord(g_ev[3], 0);

    // cumsum half 0 on s1, overlapping mega GEMM half 1
    cudaStreamWaitEvent(g_s1, g_ev[2], 0);
    cumsum_ln<<<128, CLN_T, 0, g_s1>>>(val, kc, ks, qc, qs, ln_g, ln_b, kh,
                                       Bb / 2, S, D, csp, inv_sqrt_S);
    cudaEventRecord(g_ev[4], g_s1);

    // cumsum half 1 on s1 (after mega half 1)
    cudaStreamWaitEvent(g_s1, g_ev[3], 0);
    cumsum_ln<<<128, CLN_T, 0, g_s1>>>(val + offE, kc + offE, ks + offE,
                                       qc + offE, qs + offE, ln_g, ln_b,
                                       kh + offE, Bb / 2, S, D, csp, inv_sqrt_S);
    cudaEventRecord(g_ev[5], g_s1);

    // ortho branch on s2 (needs full kc/ks -> after mega half 1)
    cudaStreamWaitEvent(g_s2, g_ev[3], 0);
    ortho_partial<<<Bb * n * n, 256, 0, g_s2>>>(kc, ks, idx, S, D, n);
    ortho_reduce<<<1, 256, 0, g_s2>>>(out + (out_size - 1), Bb * n * n, denom);
    cudaEventRecord(g_ev[6], g_s2);

    // final GEMM half 0 (default), overlaps cumsum half 1
    cudaStreamWaitEvent(0, g_ev[4], 0);
    mma_gemm<3><<<outGrid, NTHREADS, GSMEM>>>(
        kh, nullptr, WSLOT(3), nullptr, bo, nullptr, nullptr,
        out, nullptr, nullptr, nullptr, nullptr, nullptr, x, Mh, D, D);

    // final GEMM half 1
    cudaStreamWaitEvent(0, g_ev[5], 0);
    mma_gemm<3><<<outGrid, NTHREADS, GSMEM>>>(
        kh + offE, nullptr, WSLOT(3), nullptr, bo, nullptr, nullptr,
        out + offE, nullptr, nullptr, nullptr, nullptr, nullptr,
        x + offE, Mh, D, D);

    // join ortho
    cudaStreamWaitEvent(0, g_ev[6], 0);
}